// round 3
// baseline (speedup 1.0000x reference)
#include <cuda_runtime.h>
#include <cuda_bf16.h>
#include <cstdint>

#define B_  4
#define C_  256
#define CQ_ 64
#define N_  4096

static const size_t ATTN_ELEMS = (size_t)B_ * N_ * N_;   // 67108864
static const size_t OUT_ELEMS  = (size_t)B_ * C_ * N_;   // 4194304

// ---------------- scratch (__device__ globals: the allowed scratch path) ----
__device__ float g_qT [(size_t)B_ * N_ * CQ_];   // (b, n, 64)
__device__ float g_k1T[(size_t)B_ * N_ * CQ_];
__device__ float g_k2T[(size_t)B_ * N_ * CQ_];
__device__ float g_v  [(size_t)B_ * C_ * N_];    // (b, c, n)
__device__ float g_vt [(size_t)B_ * C_ * N_];
__device__ float g_E2 [(size_t)B_ * N_ * N_];    // 256 MB: exp(q.k2)

// ---------------------------------------------------------------------------
// Projection: Y = W(OxC) @ X(b,C,N) + bias.
// TRANSOUT=1: Y[b][n][O] (for q/k, O=64). TRANSOUT=0: Y[b][O][n] (for v/vt).
// Tile 64o x 64n, K=256, KT=16. 256 threads, 4x4 per thread.
// ---------------------------------------------------------------------------
template<int TRANSOUT>
__global__ void proj_kernel(const float* __restrict__ W, const float* __restrict__ bias,
                            const float* __restrict__ X, float* __restrict__ Y, int O)
{
    __shared__ float Ws[16][68];
    __shared__ float Xs[16][68];
    const int b  = blockIdx.z;
    const int n0 = blockIdx.x * 64;
    const int o0 = blockIdx.y * 64;
    const int t  = threadIdx.x;
    const int ty = t / 16, tx = t % 16;
    const float* Xb = X + (size_t)b * C_ * N_;

    float acc[4][4] = {};
    for (int k0 = 0; k0 < C_; k0 += 16) {
        // W tile: 64 o x 16 k -> Ws[k][o]
        {
            int o = t / 4, k4 = (t % 4) * 4;
            float4 w = *(const float4*)&W[(size_t)(o0 + o) * C_ + k0 + k4];
            Ws[k4 + 0][o] = w.x; Ws[k4 + 1][o] = w.y;
            Ws[k4 + 2][o] = w.z; Ws[k4 + 3][o] = w.w;
        }
        // X tile: 16 k x 64 n -> Xs[k][n]
        {
            int kk = t / 16, n4 = (t % 16) * 4;
            float4 xv = *(const float4*)&Xb[(size_t)(k0 + kk) * N_ + n0 + n4];
            *(float4*)&Xs[kk][n4] = xv;
        }
        __syncthreads();
#pragma unroll
        for (int kk = 0; kk < 16; kk++) {
            float4 wv = *(const float4*)&Ws[kk][ty * 4];
            float4 xv = *(const float4*)&Xs[kk][tx * 4];
            float wa[4] = {wv.x, wv.y, wv.z, wv.w};
            float xa[4] = {xv.x, xv.y, xv.z, xv.w};
#pragma unroll
            for (int i = 0; i < 4; i++)
#pragma unroll
                for (int j = 0; j < 4; j++)
                    acc[i][j] += wa[i] * xa[j];
        }
        __syncthreads();
    }

    float bv[4];
#pragma unroll
    for (int i = 0; i < 4; i++) bv[i] = bias[o0 + ty * 4 + i];

    if (TRANSOUT) {
        // Y[b][n][o], O == 64
#pragma unroll
        for (int i = 0; i < 4; i++)
#pragma unroll
            for (int j = 0; j < 4; j++) {
                int n = n0 + tx * 4 + j;
                int o = o0 + ty * 4 + i;
                Y[((size_t)b * N_ + n) * 64 + o] = acc[i][j] + bv[i];
            }
    } else {
#pragma unroll
        for (int i = 0; i < 4; i++) {
            int o = o0 + ty * 4 + i;
            float4 r;
            r.x = acc[i][0] + bv[i]; r.y = acc[i][1] + bv[i];
            r.z = acc[i][2] + bv[i]; r.w = acc[i][3] + bv[i];
            *(float4*)&Y[((size_t)b * O + o) * N_ + n0 + tx * 4] = r;
        }
    }
}

// ---------------------------------------------------------------------------
// QK dual GEMM + exp epilogue.
// E1[b][n][m] = exp(sum_ch qT[b][n][ch] * k1T[b][m][ch]), E2 likewise.
// Tile 64n x 64m, K=64 (single K tile). 256 threads, 4x4x2 per thread.
// No max-subtraction: |logit| <~ 35 << 88, softmax shift cancels exactly.
// ---------------------------------------------------------------------------
__global__ void qk_kernel(const float* __restrict__ qT, const float* __restrict__ k1T,
                          const float* __restrict__ k2T, float* __restrict__ E1)
{
    extern __shared__ float sm[];
    float* Qs  = sm;                 // [64][68] -> Qs[ch*68 + n]
    float* K1s = sm + 64 * 68;
    float* K2s = sm + 2 * 64 * 68;

    const int b  = blockIdx.z;
    const int m0 = blockIdx.x * 64;
    const int n0 = blockIdx.y * 64;
    const int t  = threadIdx.x;
    const int ty = t / 16, tx = t % 16;

    const float* qb  = qT  + ((size_t)b * N_ + n0) * 64;
    const float* k1b = k1T + ((size_t)b * N_ + m0) * 64;
    const float* k2b = k2T + ((size_t)b * N_ + m0) * 64;

    // load + transpose: 64 rows x 64 ch each (1024 float4 / matrix, 4 / thread)
#pragma unroll
    for (int it = 0; it < 4; it++) {
        int idx = t + 256 * it;
        int row = idx / 16, c4 = (idx % 16) * 4;
        float4 q = *(const float4*)&qb [(size_t)row * 64 + c4];
        Qs [(c4 + 0) * 68 + row] = q.x; Qs [(c4 + 1) * 68 + row] = q.y;
        Qs [(c4 + 2) * 68 + row] = q.z; Qs [(c4 + 3) * 68 + row] = q.w;
        float4 a = *(const float4*)&k1b[(size_t)row * 64 + c4];
        K1s[(c4 + 0) * 68 + row] = a.x; K1s[(c4 + 1) * 68 + row] = a.y;
        K1s[(c4 + 2) * 68 + row] = a.z; K1s[(c4 + 3) * 68 + row] = a.w;
        float4 c = *(const float4*)&k2b[(size_t)row * 64 + c4];
        K2s[(c4 + 0) * 68 + row] = c.x; K2s[(c4 + 1) * 68 + row] = c.y;
        K2s[(c4 + 2) * 68 + row] = c.z; K2s[(c4 + 3) * 68 + row] = c.w;
    }
    __syncthreads();

    float acc1[4][4] = {}, acc2[4][4] = {};
#pragma unroll 8
    for (int ch = 0; ch < 64; ch++) {
        float4 qv  = *(const float4*)&Qs [ch * 68 + ty * 4];
        float4 k1v = *(const float4*)&K1s[ch * 68 + tx * 4];
        float4 k2v = *(const float4*)&K2s[ch * 68 + tx * 4];
        float qa[4]  = {qv.x, qv.y, qv.z, qv.w};
        float k1a[4] = {k1v.x, k1v.y, k1v.z, k1v.w};
        float k2a[4] = {k2v.x, k2v.y, k2v.z, k2v.w};
#pragma unroll
        for (int i = 0; i < 4; i++)
#pragma unroll
            for (int j = 0; j < 4; j++) {
                acc1[i][j] += qa[i] * k1a[j];
                acc2[i][j] += qa[i] * k2a[j];
            }
    }

#pragma unroll
    for (int i = 0; i < 4; i++) {
        size_t off = ((size_t)b * N_ + n0 + ty * 4 + i) * N_ + m0 + tx * 4;
        float4 e1, e2;
        e1.x = __expf(acc1[i][0]); e1.y = __expf(acc1[i][1]);
        e1.z = __expf(acc1[i][2]); e1.w = __expf(acc1[i][3]);
        e2.x = __expf(acc2[i][0]); e2.y = __expf(acc2[i][1]);
        e2.z = __expf(acc2[i][2]); e2.w = __expf(acc2[i][3]);
        *(float4*)&E1[off]  = e1;
        *(float4*)&g_E2[off] = e2;
    }
}

// ---------------------------------------------------------------------------
// Per-row: d1 = sum E1, d2 = sum E2; e = exp(E1/d1 + E2/d2) (arg in (0,2],
// no shift needed); S = sum e; write attn = e/S in place over E1 (d_out).
// One block per (b, n) row; both rows cached in smem.
// ---------------------------------------------------------------------------
__global__ void softmax2_kernel(float* __restrict__ attn)
{
    __shared__ float r1[N_];
    __shared__ float r2[N_];
    __shared__ float red[256];
    const int b = blockIdx.y, n = blockIdx.x, t = threadIdx.x;
    float* row1 = attn + ((size_t)b * N_ + n) * N_;
    const float* row2 = g_E2 + ((size_t)b * N_ + n) * N_;

    float s1 = 0.f, s2 = 0.f;
#pragma unroll
    for (int i = 0; i < 4; i++) {
        int idx = (t + 256 * i) * 4;
        float4 a = *(const float4*)&row1[idx];
        float4 c = *(const float4*)&row2[idx];
        *(float4*)&r1[idx] = a;
        *(float4*)&r2[idx] = c;
        s1 += (a.x + a.y) + (a.z + a.w);
        s2 += (c.x + c.y) + (c.z + c.w);
    }
    red[t] = s1; __syncthreads();
    for (int off = 128; off > 0; off >>= 1) { if (t < off) red[t] += red[t + off]; __syncthreads(); }
    float d1 = red[0]; __syncthreads();
    red[t] = s2; __syncthreads();
    for (int off = 128; off > 0; off >>= 1) { if (t < off) red[t] += red[t + off]; __syncthreads(); }
    float d2 = red[0]; __syncthreads();

    const float i1 = 1.f / d1, i2 = 1.f / d2;
    float s = 0.f;
#pragma unroll
    for (int i = 0; i < 4; i++) {
        int idx = (t + 256 * i) * 4;
        float4 a = *(const float4*)&r1[idx];
        float4 c = *(const float4*)&r2[idx];
        float4 e;
        e.x = __expf(a.x * i1 + c.x * i2);
        e.y = __expf(a.y * i1 + c.y * i2);
        e.z = __expf(a.z * i1 + c.z * i2);
        e.w = __expf(a.w * i1 + c.w * i2);
        *(float4*)&r1[idx] = e;
        s += (e.x + e.y) + (e.z + e.w);
    }
    red[t] = s; __syncthreads();
    for (int off = 128; off > 0; off >>= 1) { if (t < off) red[t] += red[t + off]; __syncthreads(); }
    const float invS = 1.f / red[0]; __syncthreads();

#pragma unroll
    for (int i = 0; i < 4; i++) {
        int idx = (t + 256 * i) * 4;
        float4 e = *(const float4*)&r1[idx];
        e.x *= invS; e.y *= invS; e.z *= invS; e.w *= invS;
        *(float4*)&row1[idx] = e;
    }
}

// ---------------------------------------------------------------------------
// AV dual GEMM + residual epilogue.
// out1[b][c][n] = gamma *sum_m v [b][c][m]*attn[b][n][m] + x3[b][c][n]
// out2[b][c][n] = gamma2*sum_m vt[b][c][m]*attn[b][n][m] + xt[b][c][n]
// Tile 64c x 64n, KT=32. Both outputs share the attn tile (2x intensity).
// ---------------------------------------------------------------------------
__global__ void av_kernel(const float* __restrict__ attn,
                          const float* __restrict__ x3, const float* __restrict__ xt,
                          const float* __restrict__ gma, const float* __restrict__ gma2,
                          float* __restrict__ out1, float* __restrict__ out2)
{
    __shared__ float As[32 * 68];   // As[m_local*68 + n_local]
    __shared__ float Vs[32 * 68];   // Vs[m_local*68 + c_local]
    __shared__ float Ws[32 * 68];
    const int b  = blockIdx.z;
    const int c0 = blockIdx.y * 64;
    const int n0 = blockIdx.x * 64;
    const int t  = threadIdx.x;
    const int ty = t / 16, tx = t % 16;

    const float* ab = attn + ((size_t)b * N_ + n0) * N_;
    const float* vb = g_v  + ((size_t)b * C_ + c0) * N_;
    const float* wb = g_vt + ((size_t)b * C_ + c0) * N_;

    float acc1[4][4] = {}, acc2[4][4] = {};
    for (int m0 = 0; m0 < N_; m0 += 32) {
#pragma unroll
        for (int it = 0; it < 2; it++) {
            int idx = t + 256 * it;
            int r = idx / 8 % 64;           // with it: rows 0..31, 32..63
            r = (idx / 8);
            int c4 = (idx % 8) * 4;
            float4 a = *(const float4*)&ab[(size_t)r * N_ + m0 + c4];
            As[(c4 + 0) * 68 + r] = a.x; As[(c4 + 1) * 68 + r] = a.y;
            As[(c4 + 2) * 68 + r] = a.z; As[(c4 + 3) * 68 + r] = a.w;
            float4 v4 = *(const float4*)&vb[(size_t)r * N_ + m0 + c4];
            Vs[(c4 + 0) * 68 + r] = v4.x; Vs[(c4 + 1) * 68 + r] = v4.y;
            Vs[(c4 + 2) * 68 + r] = v4.z; Vs[(c4 + 3) * 68 + r] = v4.w;
            float4 w4 = *(const float4*)&wb[(size_t)r * N_ + m0 + c4];
            Ws[(c4 + 0) * 68 + r] = w4.x; Ws[(c4 + 1) * 68 + r] = w4.y;
            Ws[(c4 + 2) * 68 + r] = w4.z; Ws[(c4 + 3) * 68 + r] = w4.w;
        }
        __syncthreads();
#pragma unroll 8
        for (int kk = 0; kk < 32; kk++) {
            float4 av = *(const float4*)&As[kk * 68 + tx * 4];
            float4 vv = *(const float4*)&Vs[kk * 68 + ty * 4];
            float4 wv = *(const float4*)&Ws[kk * 68 + ty * 4];
            float aa[4] = {av.x, av.y, av.z, av.w};
            float va[4] = {vv.x, vv.y, vv.z, vv.w};
            float wa[4] = {wv.x, wv.y, wv.z, wv.w};
#pragma unroll
            for (int i = 0; i < 4; i++)
#pragma unroll
                for (int j = 0; j < 4; j++) {
                    acc1[i][j] += va[i] * aa[j];
                    acc2[i][j] += wa[i] * aa[j];
                }
        }
        __syncthreads();
    }

    const float g = *gma, g2 = *gma2;
#pragma unroll
    for (int i = 0; i < 4; i++) {
        int c = c0 + ty * 4 + i;
        size_t o = ((size_t)b * C_ + c) * N_ + n0 + tx * 4;
        float4 xv = *(const float4*)&x3[o];
        float4 r1v;
        r1v.x = g * acc1[i][0] + xv.x; r1v.y = g * acc1[i][1] + xv.y;
        r1v.z = g * acc1[i][2] + xv.z; r1v.w = g * acc1[i][3] + xv.w;
        *(float4*)&out1[o] = r1v;
        float4 xtv = *(const float4*)&xt[o];
        float4 r2v;
        r2v.x = g2 * acc2[i][0] + xtv.x; r2v.y = g2 * acc2[i][1] + xtv.y;
        r2v.z = g2 * acc2[i][2] + xtv.z; r2v.w = g2 * acc2[i][3] + xtv.w;
        *(float4*)&out2[o] = r2v;
    }
}

// ---------------------------------------------------------------------------
extern "C" void kernel_launch(void* const* d_in, const int* in_sizes, int n_in,
                              void* d_out, int out_size)
{
    const float* x1  = (const float*)d_in[0];
    const float* x2  = (const float*)d_in[1];
    const float* x3  = (const float*)d_in[2];
    const float* xt  = (const float*)d_in[3];
    const float* Wq  = (const float*)d_in[4];
    const float* bq  = (const float*)d_in[5];
    const float* Wk  = (const float*)d_in[6];
    const float* bk  = (const float*)d_in[7];
    const float* Wk2 = (const float*)d_in[8];
    const float* bk2 = (const float*)d_in[9];
    const float* Wv  = (const float*)d_in[10];
    const float* bv  = (const float*)d_in[11];
    const float* Wv2 = (const float*)d_in[12];
    const float* bv2 = (const float*)d_in[13];
    const float* gamma  = (const float*)d_in[14];
    const float* gamma2 = (const float*)d_in[15];

    float* attn = (float*)d_out;
    float* out1 = attn + ATTN_ELEMS;
    float* out2 = out1 + OUT_ELEMS;

    float *qT, *k1T, *k2T, *vbuf, *vtbuf;
    cudaGetSymbolAddress((void**)&qT,   g_qT);
    cudaGetSymbolAddress((void**)&k1T,  g_k1T);
    cudaGetSymbolAddress((void**)&k2T,  g_k2T);
    cudaGetSymbolAddress((void**)&vbuf, g_v);
    cudaGetSymbolAddress((void**)&vtbuf,g_vt);

    dim3 blk(256);

    // projections
    proj_kernel<1><<<dim3(N_ / 64, 1, B_), blk>>>(Wq,  bq,  x3, qT,    64);
    proj_kernel<1><<<dim3(N_ / 64, 1, B_), blk>>>(Wk,  bk,  x1, k1T,   64);
    proj_kernel<1><<<dim3(N_ / 64, 1, B_), blk>>>(Wk2, bk2, x2, k2T,   64);
    proj_kernel<0><<<dim3(N_ / 64, C_ / 64, B_), blk>>>(Wv,  bv,  x3, vbuf,  C_);
    proj_kernel<0><<<dim3(N_ / 64, C_ / 64, B_), blk>>>(Wv2, bv2, xt, vtbuf, C_);

    // QK logits -> exp
    const int qk_smem = 3 * 64 * 68 * (int)sizeof(float);
    cudaFuncSetAttribute(qk_kernel, cudaFuncAttributeMaxDynamicSharedMemorySize, qk_smem);
    qk_kernel<<<dim3(N_ / 64, N_ / 64, B_), blk, qk_smem>>>(qT, k1T, k2T, attn);

    // double softmax + normalize (writes final attn in place)
    softmax2_kernel<<<dim3(N_, B_), blk>>>(attn);

    // AV dual GEMM + residual
    av_kernel<<<dim3(N_ / 64, C_ / 64, B_), blk>>>(attn, x3, xt, gamma, gamma2, out1, out2);
}

// round 5
// speedup vs baseline: 2.1668x; 2.1668x over previous
#include <cuda_runtime.h>
#include <cuda_bf16.h>
#include <cstdint>

#define B_  4
#define C_  256
#define CQ_ 64
#define N_  4096

static const size_t ATTN_ELEMS = (size_t)B_ * N_ * N_;   // 67108864
static const size_t OUT_ELEMS  = (size_t)B_ * C_ * N_;   // 4194304

// ---------------- scratch (__device__ globals) ------------------------------
__device__ float g_qT [(size_t)B_ * N_ * CQ_];   // (b, n, 64)
__device__ float g_k1T[(size_t)B_ * N_ * CQ_];
__device__ float g_k2T[(size_t)B_ * N_ * CQ_];
__device__ __nv_bfloat16 g_vbf   [(size_t)B_ * C_ * N_];   // (b, c, m) bf16
__device__ __nv_bfloat16 g_vtbf  [(size_t)B_ * C_ * N_];
__device__ __nv_bfloat16 g_attnbf[(size_t)B_ * N_ * N_];   // (b, n, m) bf16
__device__ float g_E2 [(size_t)B_ * N_ * N_];    // 256 MB: exp(q.k2)

// ======================= PTX helpers (compute_103-safe) =====================
__device__ __forceinline__ uint32_t smem_u32(const void* p) {
    uint32_t a;
    asm("{ .reg .u64 t; cvta.to.shared.u64 t, %1; cvt.u32.u64 %0, t; }" : "=r"(a) : "l"(p));
    return a;
}
#define CP_ASYNC16(sdst, gsrc) asm volatile("cp.async.cg.shared.global [%0], [%1], 16;" :: "r"(sdst), "l"(gsrc))
#define CP_ASYNC_COMMIT()      asm volatile("cp.async.commit_group;" ::: "memory")
#define CP_ASYNC_WAIT0()       asm volatile("cp.async.wait_group 0;" ::: "memory")
#define CP_ASYNC_WAIT1()       asm volatile("cp.async.wait_group 1;" ::: "memory")

#define LDMATRIX_X4(r0, r1, r2, r3, addr) \
    asm volatile("ldmatrix.sync.aligned.m8n8.x4.shared.b16 {%0,%1,%2,%3}, [%4];" \
        : "=r"(r0), "=r"(r1), "=r"(r2), "=r"(r3) : "r"(addr))

#define MMA_BF16(d, a, b) \
    asm volatile("mma.sync.aligned.m16n8k16.row.col.f32.bf16.bf16.f32 " \
        "{%0,%1,%2,%3}, {%4,%5,%6,%7}, {%8,%9}, {%0,%1,%2,%3};" \
        : "+f"((d)[0]), "+f"((d)[1]), "+f"((d)[2]), "+f"((d)[3]) \
        : "r"((a)[0]), "r"((a)[1]), "r"((a)[2]), "r"((a)[3]), "r"((b)[0]), "r"((b)[1]))

// ---------------------------------------------------------------------------
// Projection (q/k): Y[b][n][64] fp32.  Tile 64o x 64n, K=256, KT=16.
// ---------------------------------------------------------------------------
__global__ void proj_qk_kernel(const float* __restrict__ W, const float* __restrict__ bias,
                               const float* __restrict__ X, float* __restrict__ Y)
{
    __shared__ float Ws[16][68];
    __shared__ float Xs[16][68];
    const int b  = blockIdx.z;
    const int n0 = blockIdx.x * 64;
    const int t  = threadIdx.x;
    const int ty = t / 16, tx = t % 16;
    const float* Xb = X + (size_t)b * C_ * N_;

    float acc[4][4] = {};
    for (int k0 = 0; k0 < C_; k0 += 16) {
        {
            int o = t / 4, k4 = (t % 4) * 4;
            float4 w = *(const float4*)&W[(size_t)o * C_ + k0 + k4];
            Ws[k4 + 0][o] = w.x; Ws[k4 + 1][o] = w.y;
            Ws[k4 + 2][o] = w.z; Ws[k4 + 3][o] = w.w;
        }
        {
            int kk = t / 16, n4 = (t % 16) * 4;
            *(float4*)&Xs[kk][n4] = *(const float4*)&Xb[(size_t)(k0 + kk) * N_ + n0 + n4];
        }
        __syncthreads();
#pragma unroll
        for (int kk = 0; kk < 16; kk++) {
            float4 wv = *(const float4*)&Ws[kk][ty * 4];
            float4 xv = *(const float4*)&Xs[kk][tx * 4];
            float wa[4] = {wv.x, wv.y, wv.z, wv.w};
            float xa[4] = {xv.x, xv.y, xv.z, xv.w};
#pragma unroll
            for (int i = 0; i < 4; i++)
#pragma unroll
                for (int j = 0; j < 4; j++)
                    acc[i][j] += wa[i] * xa[j];
        }
        __syncthreads();
    }
    float bv[4];
#pragma unroll
    for (int i = 0; i < 4; i++) bv[i] = bias[ty * 4 + i];
#pragma unroll
    for (int i = 0; i < 4; i++)
#pragma unroll
        for (int j = 0; j < 4; j++) {
            int n = n0 + tx * 4 + j;
            Y[((size_t)b * N_ + n) * 64 + ty * 4 + i] = acc[i][j] + bv[i];
        }
}

// ---------------------------------------------------------------------------
// Projection (v/vt): Y[b][o][n] bf16.  Tile 64o x 64n.
// ---------------------------------------------------------------------------
__global__ void proj_v_kernel(const float* __restrict__ W, const float* __restrict__ bias,
                              const float* __restrict__ X, __nv_bfloat16* __restrict__ Y)
{
    __shared__ float Ws[16][68];
    __shared__ float Xs[16][68];
    const int b  = blockIdx.z;
    const int n0 = blockIdx.x * 64;
    const int o0 = blockIdx.y * 64;
    const int t  = threadIdx.x;
    const int ty = t / 16, tx = t % 16;
    const float* Xb = X + (size_t)b * C_ * N_;

    float acc[4][4] = {};
    for (int k0 = 0; k0 < C_; k0 += 16) {
        {
            int o = t / 4, k4 = (t % 4) * 4;
            float4 w = *(const float4*)&W[(size_t)(o0 + o) * C_ + k0 + k4];
            Ws[k4 + 0][o] = w.x; Ws[k4 + 1][o] = w.y;
            Ws[k4 + 2][o] = w.z; Ws[k4 + 3][o] = w.w;
        }
        {
            int kk = t / 16, n4 = (t % 16) * 4;
            *(float4*)&Xs[kk][n4] = *(const float4*)&Xb[(size_t)(k0 + kk) * N_ + n0 + n4];
        }
        __syncthreads();
#pragma unroll
        for (int kk = 0; kk < 16; kk++) {
            float4 wv = *(const float4*)&Ws[kk][ty * 4];
            float4 xv = *(const float4*)&Xs[kk][tx * 4];
            float wa[4] = {wv.x, wv.y, wv.z, wv.w};
            float xa[4] = {xv.x, xv.y, xv.z, xv.w};
#pragma unroll
            for (int i = 0; i < 4; i++)
#pragma unroll
                for (int j = 0; j < 4; j++)
                    acc[i][j] += wa[i] * xa[j];
        }
        __syncthreads();
    }
    float bv[4];
#pragma unroll
    for (int i = 0; i < 4; i++) bv[i] = bias[o0 + ty * 4 + i];
#pragma unroll
    for (int i = 0; i < 4; i++) {
        int o = o0 + ty * 4 + i;
        size_t idx = ((size_t)b * C_ + o) * N_ + n0 + tx * 4;
        __nv_bfloat162 p0, p1;
        p0.x = __float2bfloat16(acc[i][0] + bv[i]);
        p0.y = __float2bfloat16(acc[i][1] + bv[i]);
        p1.x = __float2bfloat16(acc[i][2] + bv[i]);
        p1.y = __float2bfloat16(acc[i][3] + bv[i]);
        *(__nv_bfloat162*)&Y[idx]     = p0;
        *(__nv_bfloat162*)&Y[idx + 2] = p1;
    }
}

// ---------------------------------------------------------------------------
// QK dual GEMM + exp epilogue (fp32: attn output accuracy requires it).
// ---------------------------------------------------------------------------
__global__ void qk_kernel(const float* __restrict__ qT, const float* __restrict__ k1T,
                          const float* __restrict__ k2T, float* __restrict__ E1)
{
    extern __shared__ float sm[];
    float* Qs  = sm;
    float* K1s = sm + 64 * 68;
    float* K2s = sm + 2 * 64 * 68;

    const int b  = blockIdx.z;
    const int m0 = blockIdx.x * 64;
    const int n0 = blockIdx.y * 64;
    const int t  = threadIdx.x;
    const int ty = t / 16, tx = t % 16;

    const float* qb  = qT  + ((size_t)b * N_ + n0) * 64;
    const float* k1b = k1T + ((size_t)b * N_ + m0) * 64;
    const float* k2b = k2T + ((size_t)b * N_ + m0) * 64;

#pragma unroll
    for (int it = 0; it < 4; it++) {
        int idx = t + 256 * it;
        int row = idx / 16, c4 = (idx % 16) * 4;
        float4 q = *(const float4*)&qb [(size_t)row * 64 + c4];
        Qs [(c4 + 0) * 68 + row] = q.x; Qs [(c4 + 1) * 68 + row] = q.y;
        Qs [(c4 + 2) * 68 + row] = q.z; Qs [(c4 + 3) * 68 + row] = q.w;
        float4 a = *(const float4*)&k1b[(size_t)row * 64 + c4];
        K1s[(c4 + 0) * 68 + row] = a.x; K1s[(c4 + 1) * 68 + row] = a.y;
        K1s[(c4 + 2) * 68 + row] = a.z; K1s[(c4 + 3) * 68 + row] = a.w;
        float4 c = *(const float4*)&k2b[(size_t)row * 64 + c4];
        K2s[(c4 + 0) * 68 + row] = c.x; K2s[(c4 + 1) * 68 + row] = c.y;
        K2s[(c4 + 2) * 68 + row] = c.z; K2s[(c4 + 3) * 68 + row] = c.w;
    }
    __syncthreads();

    float acc1[4][4] = {}, acc2[4][4] = {};
#pragma unroll 8
    for (int ch = 0; ch < 64; ch++) {
        float4 qv  = *(const float4*)&Qs [ch * 68 + ty * 4];
        float4 k1v = *(const float4*)&K1s[ch * 68 + tx * 4];
        float4 k2v = *(const float4*)&K2s[ch * 68 + tx * 4];
        float qa[4]  = {qv.x, qv.y, qv.z, qv.w};
        float k1a[4] = {k1v.x, k1v.y, k1v.z, k1v.w};
        float k2a[4] = {k2v.x, k2v.y, k2v.z, k2v.w};
#pragma unroll
        for (int i = 0; i < 4; i++)
#pragma unroll
            for (int j = 0; j < 4; j++) {
                acc1[i][j] += qa[i] * k1a[j];
                acc2[i][j] += qa[i] * k2a[j];
            }
    }

#pragma unroll
    for (int i = 0; i < 4; i++) {
        size_t off = ((size_t)b * N_ + n0 + ty * 4 + i) * N_ + m0 + tx * 4;
        float4 e1, e2;
        e1.x = __expf(acc1[i][0]); e1.y = __expf(acc1[i][1]);
        e1.z = __expf(acc1[i][2]); e1.w = __expf(acc1[i][3]);
        e2.x = __expf(acc2[i][0]); e2.y = __expf(acc2[i][1]);
        e2.z = __expf(acc2[i][2]); e2.w = __expf(acc2[i][3]);
        *(float4*)&E1[off]   = e1;
        *(float4*)&g_E2[off] = e2;
    }
}

// ---------------------------------------------------------------------------
// Double softmax; writes fp32 attn in place (d_out) + bf16 copy for the AV MMA.
// ---------------------------------------------------------------------------
__global__ void softmax2_kernel(float* __restrict__ attn, __nv_bfloat16* __restrict__ attn_bf)
{
    __shared__ float r1[N_];
    __shared__ float r2[N_];
    __shared__ float red[256];
    const int b = blockIdx.y, n = blockIdx.x, t = threadIdx.x;
    float* row1 = attn + ((size_t)b * N_ + n) * N_;
    const float* row2 = g_E2 + ((size_t)b * N_ + n) * N_;
    __nv_bfloat16* rowb = attn_bf + ((size_t)b * N_ + n) * N_;

    float s1 = 0.f, s2 = 0.f;
#pragma unroll
    for (int i = 0; i < 4; i++) {
        int idx = (t + 256 * i) * 4;
        float4 a = *(const float4*)&row1[idx];
        float4 c = *(const float4*)&row2[idx];
        *(float4*)&r1[idx] = a;
        *(float4*)&r2[idx] = c;
        s1 += (a.x + a.y) + (a.z + a.w);
        s2 += (c.x + c.y) + (c.z + c.w);
    }
    red[t] = s1; __syncthreads();
    for (int off = 128; off > 0; off >>= 1) { if (t < off) red[t] += red[t + off]; __syncthreads(); }
    float d1 = red[0]; __syncthreads();
    red[t] = s2; __syncthreads();
    for (int off = 128; off > 0; off >>= 1) { if (t < off) red[t] += red[t + off]; __syncthreads(); }
    float d2 = red[0]; __syncthreads();

    const float i1 = 1.f / d1, i2 = 1.f / d2;
    float s = 0.f;
#pragma unroll
    for (int i = 0; i < 4; i++) {
        int idx = (t + 256 * i) * 4;
        float4 a = *(const float4*)&r1[idx];
        float4 c = *(const float4*)&r2[idx];
        float4 e;
        e.x = __expf(a.x * i1 + c.x * i2);
        e.y = __expf(a.y * i1 + c.y * i2);
        e.z = __expf(a.z * i1 + c.z * i2);
        e.w = __expf(a.w * i1 + c.w * i2);
        *(float4*)&r1[idx] = e;
        s += (e.x + e.y) + (e.z + e.w);
    }
    red[t] = s; __syncthreads();
    for (int off = 128; off > 0; off >>= 1) { if (t < off) red[t] += red[t + off]; __syncthreads(); }
    const float invS = 1.f / red[0]; __syncthreads();

#pragma unroll
    for (int i = 0; i < 4; i++) {
        int idx = (t + 256 * i) * 4;
        float4 e = *(const float4*)&r1[idx];
        e.x *= invS; e.y *= invS; e.z *= invS; e.w *= invS;
        *(float4*)&row1[idx] = e;
        __nv_bfloat162 p0, p1;
        p0.x = __float2bfloat16(e.x); p0.y = __float2bfloat16(e.y);
        p1.x = __float2bfloat16(e.z); p1.y = __float2bfloat16(e.w);
        *(__nv_bfloat162*)&rowb[idx]     = p0;
        *(__nv_bfloat162*)&rowb[idx + 2] = p1;
    }
}

// ---------------------------------------------------------------------------
// AV dual GEMM on mma.sync bf16 (m16n8k16), fused gamma*acc + x residual.
// Block tile: 128c x 64n. K (= m dim) chunks of 64, double-buffered cp.async.
// 8 warps: 4 along c, 2 along n; warp tile 32c x 32n, dual accumulators.
// SMEM rows padded to 72 bf16 (144B): ldmatrix row stride = 4 banks mod 32
// -> all 8 addresses of each 8x8 load hit distinct bank groups.
// ---------------------------------------------------------------------------
#define AV_SROW   72              // padded row stride in bf16 elems (144 B)
#define AV_VOFF   0               // Vs:  128 rows
#define AV_WOFF   (128 * AV_SROW) // Ws:  128 rows
#define AV_AOFF   (256 * AV_SROW) // As:   64 rows
#define AV_STAGE  (320 * AV_SROW) // elems per stage (23040 -> 46080 B)
#define AV_SMEM_TOTAL (2 * AV_STAGE * 2)

__device__ __forceinline__ void av_issue(uint32_t sb, const __nv_bfloat16* gv,
                                         const __nv_bfloat16* gw, const __nv_bfloat16* ga,
                                         int m0, int t)
{
    // v / vt: 128 rows x 8 16B-chunks = 1024 chunks each; attn: 64 rows -> 512.
#pragma unroll
    for (int it = 0; it < 4; it++) {
        int idx = t + 256 * it;
        int row = idx >> 3, q = idx & 7;
        uint32_t d = sb + (uint32_t)(row * 144 + q * 16);
        CP_ASYNC16(d, (const char*)(gv + (size_t)row * N_ + m0) + q * 16);
        CP_ASYNC16(d + AV_WOFF * 2, (const char*)(gw + (size_t)row * N_ + m0) + q * 16);
    }
#pragma unroll
    for (int it = 0; it < 2; it++) {
        int idx = t + 256 * it;
        int row = idx >> 3, q = idx & 7;
        uint32_t d = sb + AV_AOFF * 2 + (uint32_t)(row * 144 + q * 16);
        CP_ASYNC16(d, (const char*)(ga + (size_t)row * N_ + m0) + q * 16);
    }
}

__global__ void __launch_bounds__(256, 2)
av_mma_kernel(const float* __restrict__ x3, const float* __restrict__ xt,
              const float* __restrict__ gma, const float* __restrict__ gma2,
              float* __restrict__ out1, float* __restrict__ out2)
{
    extern __shared__ __align__(16) __nv_bfloat16 smem[];
    const uint32_t sbase = smem_u32(smem);
    const int t = threadIdx.x;
    const int wid = t / 32, lane = t % 32;
    const int wc = wid >> 1, wn = wid & 1;   // warp tile: c += 32*wc, n += 32*wn

    const int b  = blockIdx.z;
    const int c0 = blockIdx.y * 128;
    const int n0 = blockIdx.x * 64;

    const __nv_bfloat16* vb = g_vbf    + ((size_t)b * C_ + c0) * N_;
    const __nv_bfloat16* wb = g_vtbf   + ((size_t)b * C_ + c0) * N_;
    const __nv_bfloat16* ab = g_attnbf + ((size_t)b * N_ + n0) * N_;

    float acc1[2][4][4] = {}, acc2[2][4][4] = {};

    // ldmatrix lane addressing (constant across k-steps except k offset)
    const int g      = lane >> 3;          // 0..3
    const int arow   = wc * 32 + ((g & 1) ? 8 : 0) + (lane & 7);  // + mi*16
    const int akoff  = (g >> 1) * 8;                              // + kk*16
    const int brow   = wn * 32 + ((g & 1) ? 8 : 0) + (lane & 7);  // + j2*16
    const int bkoff  = (g >> 1) * 8;

    av_issue(sbase, vb, wb, ab, 0, t);
    CP_ASYNC_COMMIT();

    for (int i = 0; i < 64; i++) {
        if (i + 1 < 64) {
            av_issue(sbase + ((i + 1) & 1) * AV_STAGE * 2, vb, wb, ab, (i + 1) * 64, t);
            CP_ASYNC_COMMIT();
            CP_ASYNC_WAIT1();
        } else {
            CP_ASYNC_WAIT0();
        }
        __syncthreads();

        const uint32_t st = sbase + (i & 1) * AV_STAGE * 2;
#pragma unroll
        for (int kk = 0; kk < 4; kk++) {
            uint32_t av[2][4], aw[2][4], bfr[4][2];
#pragma unroll
            for (int mi = 0; mi < 2; mi++) {
                uint32_t aaddr = st + AV_VOFF * 2 +
                    (uint32_t)((arow + mi * 16) * 144 + (kk * 16 + akoff) * 2);
                LDMATRIX_X4(av[mi][0], av[mi][1], av[mi][2], av[mi][3], aaddr);
                uint32_t waddr = st + AV_WOFF * 2 +
                    (uint32_t)((arow + mi * 16) * 144 + (kk * 16 + akoff) * 2);
                LDMATRIX_X4(aw[mi][0], aw[mi][1], aw[mi][2], aw[mi][3], waddr);
            }
#pragma unroll
            for (int j2 = 0; j2 < 2; j2++) {
                uint32_t r0, r1, r2, r3;
                uint32_t baddr = st + AV_AOFF * 2 +
                    (uint32_t)((brow + j2 * 16) * 144 + (kk * 16 + bkoff) * 2);
                LDMATRIX_X4(r0, r1, r2, r3, baddr);
                bfr[j2 * 2 + 0][0] = r0; bfr[j2 * 2 + 0][1] = r2;
                bfr[j2 * 2 + 1][0] = r1; bfr[j2 * 2 + 1][1] = r3;
            }
#pragma unroll
            for (int mi = 0; mi < 2; mi++)
#pragma unroll
                for (int j = 0; j < 4; j++) {
                    MMA_BF16(acc1[mi][j], av[mi], bfr[j]);
                    MMA_BF16(acc2[mi][j], aw[mi], bfr[j]);
                }
        }
        __syncthreads();
    }

    // Epilogue: fragment layout m16n8 -> lane = 4*row_in_8 + col_pair
    const float gv1 = gma[0], gv2 = gma2[0];
    const int gid = lane >> 2, tig = lane & 3;
#pragma unroll
    for (int mi = 0; mi < 2; mi++) {
#pragma unroll
        for (int rr = 0; rr < 2; rr++) {   // rows gid and gid+8
            int c = c0 + wc * 32 + mi * 16 + gid + rr * 8;
            size_t rowoff = ((size_t)b * C_ + c) * N_;
#pragma unroll
            for (int j = 0; j < 4; j++) {
                int n = n0 + wn * 32 + j * 8 + tig * 2;
                float2 xv = *(const float2*)&x3[rowoff + n];
                float2 o1;
                o1.x = gv1 * acc1[mi][j][rr * 2 + 0] + xv.x;
                o1.y = gv1 * acc1[mi][j][rr * 2 + 1] + xv.y;
                *(float2*)&out1[rowoff + n] = o1;
                float2 xtv = *(const float2*)&xt[rowoff + n];
                float2 o2;
                o2.x = gv2 * acc2[mi][j][rr * 2 + 0] + xtv.x;
                o2.y = gv2 * acc2[mi][j][rr * 2 + 1] + xtv.y;
                *(float2*)&out2[rowoff + n] = o2;
            }
        }
    }
}

// ---------------------------------------------------------------------------
extern "C" void kernel_launch(void* const* d_in, const int* in_sizes, int n_in,
                              void* d_out, int out_size)
{
    const float* x1  = (const float*)d_in[0];
    const float* x2  = (const float*)d_in[1];
    const float* x3  = (const float*)d_in[2];
    const float* xt  = (const float*)d_in[3];
    const float* Wq  = (const float*)d_in[4];
    const float* bq  = (const float*)d_in[5];
    const float* Wk  = (const float*)d_in[6];
    const float* bk  = (const float*)d_in[7];
    const float* Wk2 = (const float*)d_in[8];
    const float* bk2 = (const float*)d_in[9];
    const float* Wv  = (const float*)d_in[10];
    const float* bv  = (const float*)d_in[11];
    const float* Wv2 = (const float*)d_in[12];
    const float* bv2 = (const float*)d_in[13];
    const float* gamma  = (const float*)d_in[14];
    const float* gamma2 = (const float*)d_in[15];

    float* attn = (float*)d_out;
    float* out1 = attn + ATTN_ELEMS;
    float* out2 = out1 + OUT_ELEMS;

    float *qT, *k1T, *k2T;
    __nv_bfloat16 *vbf, *vtbf, *attnbf;
    cudaGetSymbolAddress((void**)&qT,     g_qT);
    cudaGetSymbolAddress((void**)&k1T,    g_k1T);
    cudaGetSymbolAddress((void**)&k2T,    g_k2T);
    cudaGetSymbolAddress((void**)&vbf,    g_vbf);
    cudaGetSymbolAddress((void**)&vtbf,   g_vtbf);
    cudaGetSymbolAddress((void**)&attnbf, g_attnbf);

    dim3 blk(256);

    // projections
    proj_qk_kernel<<<dim3(N_ / 64, 1, B_), blk>>>(Wq,  bq,  x3, qT);
    proj_qk_kernel<<<dim3(N_ / 64, 1, B_), blk>>>(Wk,  bk,  x1, k1T);
    proj_qk_kernel<<<dim3(N_ / 64, 1, B_), blk>>>(Wk2, bk2, x2, k2T);
    proj_v_kernel<<<dim3(N_ / 64, C_ / 64, B_), blk>>>(Wv,  bv,  x3, vbf);
    proj_v_kernel<<<dim3(N_ / 64, C_ / 64, B_), blk>>>(Wv2, bv2, xt, vtbf);

    // QK logits -> exp (fp32)
    const int qk_smem = 3 * 64 * 68 * (int)sizeof(float);
    cudaFuncSetAttribute(qk_kernel, cudaFuncAttributeMaxDynamicSharedMemorySize, qk_smem);
    qk_kernel<<<dim3(N_ / 64, N_ / 64, B_), blk, qk_smem>>>(qT, k1T, k2T, attn);

    // double softmax + normalize + bf16 attn copy
    softmax2_kernel<<<dim3(N_, B_), blk>>>(attn, attnbf);

    // AV dual GEMM on mma.sync bf16 + residual epilogue
    cudaFuncSetAttribute(av_mma_kernel, cudaFuncAttributeMaxDynamicSharedMemorySize, AV_SMEM_TOTAL);
    av_mma_kernel<<<dim3(N_ / 64, C_ / 128, B_), blk, AV_SMEM_TOTAL>>>(
        x3, xt, gamma, gamma2, out1, out2);
}

// round 7
// speedup vs baseline: 2.9413x; 1.3574x over previous
#include <cuda_runtime.h>
#include <cuda_bf16.h>
#include <cstdint>

#define B_  4
#define C_  256
#define CQ_ 64
#define N_  4096

static const size_t ATTN_ELEMS = (size_t)B_ * N_ * N_;   // 67108864
static const size_t OUT_ELEMS  = (size_t)B_ * C_ * N_;   // 4194304

// ---------------- scratch (__device__ globals) ------------------------------
__device__ __nv_bfloat16 g_qhi [(size_t)B_ * N_ * CQ_];  // (b, n, 64) split bf16
__device__ __nv_bfloat16 g_qlo [(size_t)B_ * N_ * CQ_];
__device__ __nv_bfloat16 g_k1hi[(size_t)B_ * N_ * CQ_];
__device__ __nv_bfloat16 g_k1lo[(size_t)B_ * N_ * CQ_];
__device__ __nv_bfloat16 g_k2hi[(size_t)B_ * N_ * CQ_];
__device__ __nv_bfloat16 g_k2lo[(size_t)B_ * N_ * CQ_];
__device__ __nv_bfloat16 g_vbf   [(size_t)B_ * C_ * N_];   // (b, c, m) bf16
__device__ __nv_bfloat16 g_vtbf  [(size_t)B_ * C_ * N_];
__device__ __nv_bfloat16 g_attnbf[(size_t)B_ * N_ * N_];   // (b, n, m) bf16
__device__ float g_E2 [(size_t)B_ * N_ * N_];    // 256 MB: exp(q.k2)

// ======================= PTX helpers (compute_103-safe) =====================
__device__ __forceinline__ uint32_t smem_u32(const void* p) {
    uint32_t a;
    asm("{ .reg .u64 t; cvta.to.shared.u64 t, %1; cvt.u32.u64 %0, t; }" : "=r"(a) : "l"(p));
    return a;
}
#define CP_ASYNC16(sdst, gsrc) asm volatile("cp.async.cg.shared.global [%0], [%1], 16;" :: "r"(sdst), "l"(gsrc))
#define CP_ASYNC_COMMIT()      asm volatile("cp.async.commit_group;" ::: "memory")
#define CP_ASYNC_WAIT0()       asm volatile("cp.async.wait_group 0;" ::: "memory")
#define CP_ASYNC_WAIT1()       asm volatile("cp.async.wait_group 1;" ::: "memory")

#define LDMATRIX_X4(r0, r1, r2, r3, addr) \
    asm volatile("ldmatrix.sync.aligned.m8n8.x4.shared.b16 {%0,%1,%2,%3}, [%4];" \
        : "=r"(r0), "=r"(r1), "=r"(r2), "=r"(r3) : "r"(addr))

#define MMA_BF16(d, a, b) \
    asm volatile("mma.sync.aligned.m16n8k16.row.col.f32.bf16.bf16.f32 " \
        "{%0,%1,%2,%3}, {%4,%5,%6,%7}, {%8,%9}, {%0,%1,%2,%3};" \
        : "+f"((d)[0]), "+f"((d)[1]), "+f"((d)[2]), "+f"((d)[3]) \
        : "r"((a)[0]), "r"((a)[1]), "r"((a)[2]), "r"((a)[3]), "r"((b)[0]), "r"((b)[1]))

// ---------------------------------------------------------------------------
// Projection (q/k): hi/lo split bf16 output, Y[b][n][64].  64o x 64n, KT=16.
// ---------------------------------------------------------------------------
__global__ void proj_qk_kernel(const float* __restrict__ W, const float* __restrict__ bias,
                               const float* __restrict__ X,
                               __nv_bfloat16* __restrict__ Yhi,
                               __nv_bfloat16* __restrict__ Ylo)
{
    __shared__ float Ws[16][68];
    __shared__ float Xs[16][68];
    const int b  = blockIdx.z;
    const int n0 = blockIdx.x * 64;
    const int t  = threadIdx.x;
    const int ty = t / 16, tx = t % 16;
    const float* Xb = X + (size_t)b * C_ * N_;

    float acc[4][4] = {};
    for (int k0 = 0; k0 < C_; k0 += 16) {
        {
            int o = t / 4, k4 = (t % 4) * 4;
            float4 w = *(const float4*)&W[(size_t)o * C_ + k0 + k4];
            Ws[k4 + 0][o] = w.x; Ws[k4 + 1][o] = w.y;
            Ws[k4 + 2][o] = w.z; Ws[k4 + 3][o] = w.w;
        }
        {
            int kk = t / 16, n4 = (t % 16) * 4;
            *(float4*)&Xs[kk][n4] = *(const float4*)&Xb[(size_t)(k0 + kk) * N_ + n0 + n4];
        }
        __syncthreads();
#pragma unroll
        for (int kk = 0; kk < 16; kk++) {
            float4 wv = *(const float4*)&Ws[kk][ty * 4];
            float4 xv = *(const float4*)&Xs[kk][tx * 4];
            float wa[4] = {wv.x, wv.y, wv.z, wv.w};
            float xa[4] = {xv.x, xv.y, xv.z, xv.w};
#pragma unroll
            for (int i = 0; i < 4; i++)
#pragma unroll
                for (int j = 0; j < 4; j++)
                    acc[i][j] += wa[i] * xa[j];
        }
        __syncthreads();
    }
    float bv[4];
#pragma unroll
    for (int i = 0; i < 4; i++) bv[i] = bias[ty * 4 + i];
#pragma unroll
    for (int i = 0; i < 4; i++)
#pragma unroll
        for (int j = 0; j < 4; j++) {
            int n = n0 + tx * 4 + j;
            float val = acc[i][j] + bv[i];
            __nv_bfloat16 hi = __float2bfloat16(val);
            float lo = val - __bfloat162float(hi);
            size_t idx = ((size_t)b * N_ + n) * 64 + ty * 4 + i;
            Yhi[idx] = hi;
            Ylo[idx] = __float2bfloat16(lo);
        }
}

// ---------------------------------------------------------------------------
// Projection (v/vt): Y[b][o][n] bf16.  Tile 64o x 64n.
// ---------------------------------------------------------------------------
__global__ void proj_v_kernel(const float* __restrict__ W, const float* __restrict__ bias,
                              const float* __restrict__ X, __nv_bfloat16* __restrict__ Y)
{
    __shared__ float Ws[16][68];
    __shared__ float Xs[16][68];
    const int b  = blockIdx.z;
    const int n0 = blockIdx.x * 64;
    const int o0 = blockIdx.y * 64;
    const int t  = threadIdx.x;
    const int ty = t / 16, tx = t % 16;
    const float* Xb = X + (size_t)b * C_ * N_;

    float acc[4][4] = {};
    for (int k0 = 0; k0 < C_; k0 += 16) {
        {
            int o = t / 4, k4 = (t % 4) * 4;
            float4 w = *(const float4*)&W[(size_t)(o0 + o) * C_ + k0 + k4];
            Ws[k4 + 0][o] = w.x; Ws[k4 + 1][o] = w.y;
            Ws[k4 + 2][o] = w.z; Ws[k4 + 3][o] = w.w;
        }
        {
            int kk = t / 16, n4 = (t % 16) * 4;
            *(float4*)&Xs[kk][n4] = *(const float4*)&Xb[(size_t)(k0 + kk) * N_ + n0 + n4];
        }
        __syncthreads();
#pragma unroll
        for (int kk = 0; kk < 16; kk++) {
            float4 wv = *(const float4*)&Ws[kk][ty * 4];
            float4 xv = *(const float4*)&Xs[kk][tx * 4];
            float wa[4] = {wv.x, wv.y, wv.z, wv.w};
            float xa[4] = {xv.x, xv.y, xv.z, xv.w};
#pragma unroll
            for (int i = 0; i < 4; i++)
#pragma unroll
                for (int j = 0; j < 4; j++)
                    acc[i][j] += wa[i] * xa[j];
        }
        __syncthreads();
    }
    float bv[4];
#pragma unroll
    for (int i = 0; i < 4; i++) bv[i] = bias[o0 + ty * 4 + i];
#pragma unroll
    for (int i = 0; i < 4; i++) {
        int o = o0 + ty * 4 + i;
        size_t idx = ((size_t)b * C_ + o) * N_ + n0 + tx * 4;
        __nv_bfloat162 p0, p1;
        p0.x = __float2bfloat16(acc[i][0] + bv[i]);
        p0.y = __float2bfloat16(acc[i][1] + bv[i]);
        p1.x = __float2bfloat16(acc[i][2] + bv[i]);
        p1.y = __float2bfloat16(acc[i][3] + bv[i]);
        *(__nv_bfloat162*)&Y[idx]     = p0;
        *(__nv_bfloat162*)&Y[idx + 2] = p1;
    }
}

// ---------------------------------------------------------------------------
// QK dual GEMM on mma.sync bf16 with hi/lo split (3 terms), fused exp.
// z = qhi.khi + qhi.klo + qlo.khi ; E1 = exp(z1) -> d_out, E2 -> g_E2.
// Block 128n x 64m, K=64 single shot. 8 warps (4n x 2m), warp 32n x 32m.
// SMEM rows padded to 144B -> conflict-free ldmatrix.
// ---------------------------------------------------------------------------
#define QK_QHI_B  0
#define QK_QLO_B  (128 * 144)
#define QK_K1HI_B (256 * 144)
#define QK_K1LO_B (320 * 144)
#define QK_K2HI_B (384 * 144)
#define QK_K2LO_B (448 * 144)
#define QK_SMEM_TOTAL (512 * 144)   // 73728 B

__global__ void __launch_bounds__(256, 2)
qk_mma_kernel(float* __restrict__ E1)
{
    extern __shared__ __align__(16) char smem[];
    const uint32_t sbase = smem_u32(smem);
    const int t = threadIdx.x;
    const int wid = t / 32, lane = t % 32;
    const int wn = wid >> 1, wm = wid & 1;   // 4 warps along n, 2 along m

    const int b  = blockIdx.z;
    const int m0 = blockIdx.x * 64;
    const int n0 = blockIdx.y * 128;

    const char* qh  = (const char*)(g_qhi  + ((size_t)b * N_ + n0) * 64);
    const char* ql  = (const char*)(g_qlo  + ((size_t)b * N_ + n0) * 64);
    const char* k1h = (const char*)(g_k1hi + ((size_t)b * N_ + m0) * 64);
    const char* k1l = (const char*)(g_k1lo + ((size_t)b * N_ + m0) * 64);
    const char* k2h = (const char*)(g_k2hi + ((size_t)b * N_ + m0) * 64);
    const char* k2l = (const char*)(g_k2lo + ((size_t)b * N_ + m0) * 64);

    // ---- load all tiles (single K pass) ----
#pragma unroll
    for (int it = 0; it < 4; it++) {           // q: 128 rows x 8 chunks, hi+lo
        int idx = t + 256 * it;
        int row = idx >> 3, q = idx & 7;
        uint32_t d = sbase + (uint32_t)(row * 144 + q * 16);
        int srco = row * 128 + q * 16;
        CP_ASYNC16(d + QK_QHI_B, qh + srco);
        CP_ASYNC16(d + QK_QLO_B, ql + srco);
    }
#pragma unroll
    for (int it = 0; it < 2; it++) {           // k1/k2: 64 rows x 8 chunks, hi+lo
        int idx = t + 256 * it;
        int row = idx >> 3, q = idx & 7;
        uint32_t d = sbase + (uint32_t)(row * 144 + q * 16);
        int srco = row * 128 + q * 16;
        CP_ASYNC16(d + QK_K1HI_B, k1h + srco);
        CP_ASYNC16(d + QK_K1LO_B, k1l + srco);
        CP_ASYNC16(d + QK_K2HI_B, k2h + srco);
        CP_ASYNC16(d + QK_K2LO_B, k2l + srco);
    }
    CP_ASYNC_COMMIT();
    CP_ASYNC_WAIT0();
    __syncthreads();

    // ---- MMA mainloop over K (4 steps of 16) ----
    const int g    = lane >> 3;
    const int arow = wn * 32 + ((g & 1) ? 8 : 0) + (lane & 7);   // + mi*16
    const int koff = (g >> 1) * 8;                               // + kk*16
    const int brow = wm * 32 + ((g & 1) ? 8 : 0) + (lane & 7);   // + j2*16

    float acc1[2][4][4] = {}, acc2[2][4][4] = {};

#pragma unroll
    for (int kk = 0; kk < 4; kk++) {
        uint32_t ah[2][4], al[2][4];
#pragma unroll
        for (int mi = 0; mi < 2; mi++) {
            uint32_t ka = (uint32_t)((arow + mi * 16) * 144 + (kk * 16 + koff) * 2);
            LDMATRIX_X4(ah[mi][0], ah[mi][1], ah[mi][2], ah[mi][3], sbase + QK_QHI_B + ka);
            LDMATRIX_X4(al[mi][0], al[mi][1], al[mi][2], al[mi][3], sbase + QK_QLO_B + ka);
        }
#pragma unroll
        for (int j2 = 0; j2 < 2; j2++) {
            uint32_t kb = (uint32_t)((brow + j2 * 16) * 144 + (kk * 16 + koff) * 2);
            uint32_t b1h[2][2], b1l[2][2], b2h[2][2], b2l[2][2];
            {
                uint32_t r0, r1, r2, r3;
                LDMATRIX_X4(r0, r1, r2, r3, sbase + QK_K1HI_B + kb);
                b1h[0][0] = r0; b1h[0][1] = r2; b1h[1][0] = r1; b1h[1][1] = r3;
                LDMATRIX_X4(r0, r1, r2, r3, sbase + QK_K1LO_B + kb);
                b1l[0][0] = r0; b1l[0][1] = r2; b1l[1][0] = r1; b1l[1][1] = r3;
                LDMATRIX_X4(r0, r1, r2, r3, sbase + QK_K2HI_B + kb);
                b2h[0][0] = r0; b2h[0][1] = r2; b2h[1][0] = r1; b2h[1][1] = r3;
                LDMATRIX_X4(r0, r1, r2, r3, sbase + QK_K2LO_B + kb);
                b2l[0][0] = r0; b2l[0][1] = r2; b2l[1][0] = r1; b2l[1][1] = r3;
            }
#pragma unroll
            for (int mi = 0; mi < 2; mi++)
#pragma unroll
                for (int jj = 0; jj < 2; jj++) {
                    int j = j2 * 2 + jj;
                    MMA_BF16(acc1[mi][j], ah[mi], b1h[jj]);
                    MMA_BF16(acc1[mi][j], ah[mi], b1l[jj]);
                    MMA_BF16(acc1[mi][j], al[mi], b1h[jj]);
                    MMA_BF16(acc2[mi][j], ah[mi], b2h[jj]);
                    MMA_BF16(acc2[mi][j], ah[mi], b2l[jj]);
                    MMA_BF16(acc2[mi][j], al[mi], b2h[jj]);
                }
        }
    }

    // ---- exp epilogue ----
    const int gid = lane >> 2, tig = lane & 3;
#pragma unroll
    for (int mi = 0; mi < 2; mi++)
#pragma unroll
        for (int rr = 0; rr < 2; rr++) {
            int n = n0 + wn * 32 + mi * 16 + gid + rr * 8;
            size_t rowoff = ((size_t)b * N_ + n) * N_;
#pragma unroll
            for (int j = 0; j < 4; j++) {
                int m = m0 + wm * 32 + j * 8 + tig * 2;
                float2 e1, e2;
                e1.x = __expf(acc1[mi][j][rr * 2 + 0]);
                e1.y = __expf(acc1[mi][j][rr * 2 + 1]);
                e2.x = __expf(acc2[mi][j][rr * 2 + 0]);
                e2.y = __expf(acc2[mi][j][rr * 2 + 1]);
                *(float2*)&E1[rowoff + m]   = e1;
                *(float2*)&g_E2[rowoff + m] = e2;
            }
        }
}

// ---------------------------------------------------------------------------
// Double softmax; writes fp32 attn in place (d_out) + bf16 copy for the AV MMA.
// ---------------------------------------------------------------------------
__global__ void softmax2_kernel(float* __restrict__ attn, __nv_bfloat16* __restrict__ attn_bf)
{
    __shared__ float r1[N_];
    __shared__ float r2[N_];
    __shared__ float red[256];
    const int b = blockIdx.y, n = blockIdx.x, t = threadIdx.x;
    float* row1 = attn + ((size_t)b * N_ + n) * N_;
    const float* row2 = g_E2 + ((size_t)b * N_ + n) * N_;
    __nv_bfloat16* rowb = attn_bf + ((size_t)b * N_ + n) * N_;

    float s1 = 0.f, s2 = 0.f;
#pragma unroll
    for (int i = 0; i < 4; i++) {
        int idx = (t + 256 * i) * 4;
        float4 a = *(const float4*)&row1[idx];
        float4 c = *(const float4*)&row2[idx];
        *(float4*)&r1[idx] = a;
        *(float4*)&r2[idx] = c;
        s1 += (a.x + a.y) + (a.z + a.w);
        s2 += (c.x + c.y) + (c.z + c.w);
    }
    red[t] = s1; __syncthreads();
    for (int off = 128; off > 0; off >>= 1) { if (t < off) red[t] += red[t + off]; __syncthreads(); }
    float d1 = red[0]; __syncthreads();
    red[t] = s2; __syncthreads();
    for (int off = 128; off > 0; off >>= 1) { if (t < off) red[t] += red[t + off]; __syncthreads(); }
    float d2 = red[0]; __syncthreads();

    const float i1 = 1.f / d1, i2 = 1.f / d2;
    float s = 0.f;
#pragma unroll
    for (int i = 0; i < 4; i++) {
        int idx = (t + 256 * i) * 4;
        float4 a = *(const float4*)&r1[idx];
        float4 c = *(const float4*)&r2[idx];
        float4 e;
        e.x = __expf(a.x * i1 + c.x * i2);
        e.y = __expf(a.y * i1 + c.y * i2);
        e.z = __expf(a.z * i1 + c.z * i2);
        e.w = __expf(a.w * i1 + c.w * i2);
        *(float4*)&r1[idx] = e;
        s += (e.x + e.y) + (e.z + e.w);
    }
    red[t] = s; __syncthreads();
    for (int off = 128; off > 0; off >>= 1) { if (t < off) red[t] += red[t + off]; __syncthreads(); }
    const float invS = 1.f / red[0]; __syncthreads();

#pragma unroll
    for (int i = 0; i < 4; i++) {
        int idx = (t + 256 * i) * 4;
        float4 e = *(const float4*)&r1[idx];
        e.x *= invS; e.y *= invS; e.z *= invS; e.w *= invS;
        *(float4*)&row1[idx] = e;
        __nv_bfloat162 p0, p1;
        p0.x = __float2bfloat16(e.x); p0.y = __float2bfloat16(e.y);
        p1.x = __float2bfloat16(e.z); p1.y = __float2bfloat16(e.w);
        *(__nv_bfloat162*)&rowb[idx]     = p0;
        *(__nv_bfloat162*)&rowb[idx + 2] = p1;
    }
}

// ---------------------------------------------------------------------------
// AV dual GEMM on mma.sync bf16 (m16n8k16), fused gamma*acc + x residual.
// Block 128c x 64n, K chunks of 64, double-buffered cp.async. 8 warps (4c x 2n).
// ---------------------------------------------------------------------------
#define AV_SROW   72
#define AV_WOFF   (128 * AV_SROW)
#define AV_AOFF   (256 * AV_SROW)
#define AV_STAGE  (320 * AV_SROW)
#define AV_SMEM_TOTAL (2 * AV_STAGE * 2)

__device__ __forceinline__ void av_issue(uint32_t sb, const __nv_bfloat16* gv,
                                         const __nv_bfloat16* gw, const __nv_bfloat16* ga,
                                         int m0, int t)
{
#pragma unroll
    for (int it = 0; it < 4; it++) {
        int idx = t + 256 * it;
        int row = idx >> 3, q = idx & 7;
        uint32_t d = sb + (uint32_t)(row * 144 + q * 16);
        CP_ASYNC16(d, (const char*)(gv + (size_t)row * N_ + m0) + q * 16);
        CP_ASYNC16(d + AV_WOFF * 2, (const char*)(gw + (size_t)row * N_ + m0) + q * 16);
    }
#pragma unroll
    for (int it = 0; it < 2; it++) {
        int idx = t + 256 * it;
        int row = idx >> 3, q = idx & 7;
        uint32_t d = sb + AV_AOFF * 2 + (uint32_t)(row * 144 + q * 16);
        CP_ASYNC16(d, (const char*)(ga + (size_t)row * N_ + m0) + q * 16);
    }
}

__global__ void __launch_bounds__(256, 2)
av_mma_kernel(const float* __restrict__ x3, const float* __restrict__ xt,
              const float* __restrict__ gma, const float* __restrict__ gma2,
              float* __restrict__ out1, float* __restrict__ out2)
{
    extern __shared__ __align__(16) char smem[];
    const uint32_t sbase = smem_u32(smem);
    const int t = threadIdx.x;
    const int wid = t / 32, lane = t % 32;
    const int wc = wid >> 1, wn = wid & 1;

    const int b  = blockIdx.z;
    const int c0 = blockIdx.y * 128;
    const int n0 = blockIdx.x * 64;

    const __nv_bfloat16* vb = g_vbf    + ((size_t)b * C_ + c0) * N_;
    const __nv_bfloat16* wb = g_vtbf   + ((size_t)b * C_ + c0) * N_;
    const __nv_bfloat16* ab = g_attnbf + ((size_t)b * N_ + n0) * N_;

    float acc1[2][4][4] = {}, acc2[2][4][4] = {};

    const int g      = lane >> 3;
    const int arow   = wc * 32 + ((g & 1) ? 8 : 0) + (lane & 7);
    const int akoff  = (g >> 1) * 8;
    const int brow   = wn * 32 + ((g & 1) ? 8 : 0) + (lane & 7);
    const int bkoff  = (g >> 1) * 8;

    av_issue(sbase, vb, wb, ab, 0, t);
    CP_ASYNC_COMMIT();

    for (int i = 0; i < 64; i++) {
        if (i + 1 < 64) {
            av_issue(sbase + ((i + 1) & 1) * AV_STAGE * 2, vb, wb, ab, (i + 1) * 64, t);
            CP_ASYNC_COMMIT();
            CP_ASYNC_WAIT1();
        } else {
            CP_ASYNC_WAIT0();
        }
        __syncthreads();

        const uint32_t st = sbase + (i & 1) * AV_STAGE * 2;
#pragma unroll
        for (int kk = 0; kk < 4; kk++) {
            uint32_t av[2][4], aw[2][4], bfr[4][2];
#pragma unroll
            for (int mi = 0; mi < 2; mi++) {
                uint32_t aaddr = st + (uint32_t)((arow + mi * 16) * 144 + (kk * 16 + akoff) * 2);
                LDMATRIX_X4(av[mi][0], av[mi][1], av[mi][2], av[mi][3], aaddr);
                uint32_t waddr = st + AV_WOFF * 2 +
                    (uint32_t)((arow + mi * 16) * 144 + (kk * 16 + akoff) * 2);
                LDMATRIX_X4(aw[mi][0], aw[mi][1], aw[mi][2], aw[mi][3], waddr);
            }
#pragma unroll
            for (int j2 = 0; j2 < 2; j2++) {
                uint32_t r0, r1, r2, r3;
                uint32_t baddr = st + AV_AOFF * 2 +
                    (uint32_t)((brow + j2 * 16) * 144 + (kk * 16 + bkoff) * 2);
                LDMATRIX_X4(r0, r1, r2, r3, baddr);
                bfr[j2 * 2 + 0][0] = r0; bfr[j2 * 2 + 0][1] = r2;
                bfr[j2 * 2 + 1][0] = r1; bfr[j2 * 2 + 1][1] = r3;
            }
#pragma unroll
            for (int mi = 0; mi < 2; mi++)
#pragma unroll
                for (int j = 0; j < 4; j++) {
                    MMA_BF16(acc1[mi][j], av[mi], bfr[j]);
                    MMA_BF16(acc2[mi][j], aw[mi], bfr[j]);
                }
        }
        __syncthreads();
    }

    const float gv1 = gma[0], gv2 = gma2[0];
    const int gid = lane >> 2, tig = lane & 3;
#pragma unroll
    for (int mi = 0; mi < 2; mi++) {
#pragma unroll
        for (int rr = 0; rr < 2; rr++) {
            int c = c0 + wc * 32 + mi * 16 + gid + rr * 8;
            size_t rowoff = ((size_t)b * C_ + c) * N_;
#pragma unroll
            for (int j = 0; j < 4; j++) {
                int n = n0 + wn * 32 + j * 8 + tig * 2;
                float2 xv = *(const float2*)&x3[rowoff + n];
                float2 o1;
                o1.x = gv1 * acc1[mi][j][rr * 2 + 0] + xv.x;
                o1.y = gv1 * acc1[mi][j][rr * 2 + 1] + xv.y;
                *(float2*)&out1[rowoff + n] = o1;
                float2 xtv = *(const float2*)&xt[rowoff + n];
                float2 o2;
                o2.x = gv2 * acc2[mi][j][rr * 2 + 0] + xtv.x;
                o2.y = gv2 * acc2[mi][j][rr * 2 + 1] + xtv.y;
                *(float2*)&out2[rowoff + n] = o2;
            }
        }
    }
}

// ---------------------------------------------------------------------------
extern "C" void kernel_launch(void* const* d_in, const int* in_sizes, int n_in,
                              void* d_out, int out_size)
{
    const float* x1  = (const float*)d_in[0];
    const float* x2  = (const float*)d_in[1];
    const float* x3  = (const float*)d_in[2];
    const float* xt  = (const float*)d_in[3];
    const float* Wq  = (const float*)d_in[4];
    const float* bq  = (const float*)d_in[5];
    const float* Wk  = (const float*)d_in[6];
    const float* bk  = (const float*)d_in[7];
    const float* Wk2 = (const float*)d_in[8];
    const float* bk2 = (const float*)d_in[9];
    const float* Wv  = (const float*)d_in[10];
    const float* bv  = (const float*)d_in[11];
    const float* Wv2 = (const float*)d_in[12];
    const float* bv2 = (const float*)d_in[13];
    const float* gamma  = (const float*)d_in[14];
    const float* gamma2 = (const float*)d_in[15];

    float* attn = (float*)d_out;
    float* out1 = attn + ATTN_ELEMS;
    float* out2 = out1 + OUT_ELEMS;

    __nv_bfloat16 *qhi, *qlo, *k1hi, *k1lo, *k2hi, *k2lo, *vbf, *vtbf, *attnbf;
    cudaGetSymbolAddress((void**)&qhi,    g_qhi);
    cudaGetSymbolAddress((void**)&qlo,    g_qlo);
    cudaGetSymbolAddress((void**)&k1hi,   g_k1hi);
    cudaGetSymbolAddress((void**)&k1lo,   g_k1lo);
    cudaGetSymbolAddress((void**)&k2hi,   g_k2hi);
    cudaGetSymbolAddress((void**)&k2lo,   g_k2lo);
    cudaGetSymbolAddress((void**)&vbf,    g_vbf);
    cudaGetSymbolAddress((void**)&vtbf,   g_vtbf);
    cudaGetSymbolAddress((void**)&attnbf, g_attnbf);

    dim3 blk(256);

    // projections (q/k emit hi/lo split bf16)
    proj_qk_kernel<<<dim3(N_ / 64, 1, B_), blk>>>(Wq,  bq,  x3, qhi,  qlo);
    proj_qk_kernel<<<dim3(N_ / 64, 1, B_), blk>>>(Wk,  bk,  x1, k1hi, k1lo);
    proj_qk_kernel<<<dim3(N_ / 64, 1, B_), blk>>>(Wk2, bk2, x2, k2hi, k2lo);
    proj_v_kernel<<<dim3(N_ / 64, C_ / 64, B_), blk>>>(Wv,  bv,  x3, vbf);
    proj_v_kernel<<<dim3(N_ / 64, C_ / 64, B_), blk>>>(Wv2, bv2, xt, vtbf);

    // QK logits on tensor cores (split bf16) -> exp
    cudaFuncSetAttribute(qk_mma_kernel, cudaFuncAttributeMaxDynamicSharedMemorySize, QK_SMEM_TOTAL);
    qk_mma_kernel<<<dim3(N_ / 64, N_ / 128, B_), blk, QK_SMEM_TOTAL>>>(attn);

    // double softmax + normalize + bf16 attn copy
    softmax2_kernel<<<dim3(N_, B_), blk>>>(attn, attnbf);

    // AV dual GEMM on mma.sync bf16 + residual epilogue
    cudaFuncSetAttribute(av_mma_kernel, cudaFuncAttributeMaxDynamicSharedMemorySize, AV_SMEM_TOTAL);
    av_mma_kernel<<<dim3(N_ / 64, C_ / 128, B_), blk, AV_SMEM_TOTAL>>>(
        x3, xt, gamma, gamma2, out1, out2);
}

// round 8
// speedup vs baseline: 3.0819x; 1.0478x over previous
#include <cuda_runtime.h>
#include <cuda_bf16.h>
#include <cstdint>

#define B_  4
#define C_  256
#define CQ_ 64
#define N_  4096

static const size_t ATTN_ELEMS = (size_t)B_ * N_ * N_;   // 67108864
static const size_t OUT_ELEMS  = (size_t)B_ * C_ * N_;   // 4194304

// ---------------- scratch (__device__ globals) ------------------------------
__device__ __nv_bfloat16 g_qhi [(size_t)B_ * N_ * CQ_];  // (b, n, 64) split bf16
__device__ __nv_bfloat16 g_qlo [(size_t)B_ * N_ * CQ_];
__device__ __nv_bfloat16 g_k1hi[(size_t)B_ * N_ * CQ_];
__device__ __nv_bfloat16 g_k1lo[(size_t)B_ * N_ * CQ_];
__device__ __nv_bfloat16 g_k2hi[(size_t)B_ * N_ * CQ_];
__device__ __nv_bfloat16 g_k2lo[(size_t)B_ * N_ * CQ_];
__device__ __nv_bfloat16 g_vbf   [(size_t)B_ * C_ * N_];   // (b, c, m) bf16
__device__ __nv_bfloat16 g_vtbf  [(size_t)B_ * C_ * N_];
__device__ __nv_bfloat16 g_attnbf[(size_t)B_ * N_ * N_];   // (b, n, m) bf16
__device__ float g_E2 [(size_t)B_ * N_ * N_];    // 256 MB: exp(q.k2)

// ======================= PTX helpers (compute_103-safe) =====================
__device__ __forceinline__ uint32_t smem_u32(const void* p) {
    uint32_t a;
    asm("{ .reg .u64 t; cvta.to.shared.u64 t, %1; cvt.u32.u64 %0, t; }" : "=r"(a) : "l"(p));
    return a;
}
#define CP_ASYNC16(sdst, gsrc) asm volatile("cp.async.cg.shared.global [%0], [%1], 16;" :: "r"(sdst), "l"(gsrc))
#define CP_ASYNC_COMMIT()      asm volatile("cp.async.commit_group;" ::: "memory")
#define CP_ASYNC_WAIT0()       asm volatile("cp.async.wait_group 0;" ::: "memory")
#define CP_ASYNC_WAIT1()       asm volatile("cp.async.wait_group 1;" ::: "memory")
#define CP_ASYNC_WAIT2()       asm volatile("cp.async.wait_group 2;" ::: "memory")

#define LDMATRIX_X4(r0, r1, r2, r3, addr) \
    asm volatile("ldmatrix.sync.aligned.m8n8.x4.shared.b16 {%0,%1,%2,%3}, [%4];" \
        : "=r"(r0), "=r"(r1), "=r"(r2), "=r"(r3) : "r"(addr))

#define MMA_BF16(d, a, b) \
    asm volatile("mma.sync.aligned.m16n8k16.row.col.f32.bf16.bf16.f32 " \
        "{%0,%1,%2,%3}, {%4,%5,%6,%7}, {%8,%9}, {%0,%1,%2,%3};" \
        : "+f"((d)[0]), "+f"((d)[1]), "+f"((d)[2]), "+f"((d)[3]) \
        : "r"((a)[0]), "r"((a)[1]), "r"((a)[2]), "r"((a)[3]), "r"((b)[0]), "r"((b)[1]))

// ---------------------------------------------------------------------------
// Projection (q/k): hi/lo split bf16 output, Y[b][n][64].  64o x 64n, KT=16.
// ---------------------------------------------------------------------------
__global__ void proj_qk_kernel(const float* __restrict__ W, const float* __restrict__ bias,
                               const float* __restrict__ X,
                               __nv_bfloat16* __restrict__ Yhi,
                               __nv_bfloat16* __restrict__ Ylo)
{
    __shared__ float Ws[16][68];
    __shared__ float Xs[16][68];
    const int b  = blockIdx.z;
    const int n0 = blockIdx.x * 64;
    const int t  = threadIdx.x;
    const int ty = t / 16, tx = t % 16;
    const float* Xb = X + (size_t)b * C_ * N_;

    float acc[4][4] = {};
    for (int k0 = 0; k0 < C_; k0 += 16) {
        {
            int o = t / 4, k4 = (t % 4) * 4;
            float4 w = *(const float4*)&W[(size_t)o * C_ + k0 + k4];
            Ws[k4 + 0][o] = w.x; Ws[k4 + 1][o] = w.y;
            Ws[k4 + 2][o] = w.z; Ws[k4 + 3][o] = w.w;
        }
        {
            int kk = t / 16, n4 = (t % 16) * 4;
            *(float4*)&Xs[kk][n4] = *(const float4*)&Xb[(size_t)(k0 + kk) * N_ + n0 + n4];
        }
        __syncthreads();
#pragma unroll
        for (int kk = 0; kk < 16; kk++) {
            float4 wv = *(const float4*)&Ws[kk][ty * 4];
            float4 xv = *(const float4*)&Xs[kk][tx * 4];
            float wa[4] = {wv.x, wv.y, wv.z, wv.w};
            float xa[4] = {xv.x, xv.y, xv.z, xv.w};
#pragma unroll
            for (int i = 0; i < 4; i++)
#pragma unroll
                for (int j = 0; j < 4; j++)
                    acc[i][j] += wa[i] * xa[j];
        }
        __syncthreads();
    }
    float bv[4];
#pragma unroll
    for (int i = 0; i < 4; i++) bv[i] = bias[ty * 4 + i];
#pragma unroll
    for (int i = 0; i < 4; i++)
#pragma unroll
        for (int j = 0; j < 4; j++) {
            int n = n0 + tx * 4 + j;
            float val = acc[i][j] + bv[i];
            __nv_bfloat16 hi = __float2bfloat16(val);
            float lo = val - __bfloat162float(hi);
            size_t idx = ((size_t)b * N_ + n) * 64 + ty * 4 + i;
            Yhi[idx] = hi;
            Ylo[idx] = __float2bfloat16(lo);
        }
}

// ---------------------------------------------------------------------------
// Projection (v/vt): Y[b][o][n] bf16.  Tile 64o x 64n.
// ---------------------------------------------------------------------------
__global__ void proj_v_kernel(const float* __restrict__ W, const float* __restrict__ bias,
                              const float* __restrict__ X, __nv_bfloat16* __restrict__ Y)
{
    __shared__ float Ws[16][68];
    __shared__ float Xs[16][68];
    const int b  = blockIdx.z;
    const int n0 = blockIdx.x * 64;
    const int o0 = blockIdx.y * 64;
    const int t  = threadIdx.x;
    const int ty = t / 16, tx = t % 16;
    const float* Xb = X + (size_t)b * C_ * N_;

    float acc[4][4] = {};
    for (int k0 = 0; k0 < C_; k0 += 16) {
        {
            int o = t / 4, k4 = (t % 4) * 4;
            float4 w = *(const float4*)&W[(size_t)(o0 + o) * C_ + k0 + k4];
            Ws[k4 + 0][o] = w.x; Ws[k4 + 1][o] = w.y;
            Ws[k4 + 2][o] = w.z; Ws[k4 + 3][o] = w.w;
        }
        {
            int kk = t / 16, n4 = (t % 16) * 4;
            *(float4*)&Xs[kk][n4] = *(const float4*)&Xb[(size_t)(k0 + kk) * N_ + n0 + n4];
        }
        __syncthreads();
#pragma unroll
        for (int kk = 0; kk < 16; kk++) {
            float4 wv = *(const float4*)&Ws[kk][ty * 4];
            float4 xv = *(const float4*)&Xs[kk][tx * 4];
            float wa[4] = {wv.x, wv.y, wv.z, wv.w};
            float xa[4] = {xv.x, xv.y, xv.z, xv.w};
#pragma unroll
            for (int i = 0; i < 4; i++)
#pragma unroll
                for (int j = 0; j < 4; j++)
                    acc[i][j] += wa[i] * xa[j];
        }
        __syncthreads();
    }
    float bv[4];
#pragma unroll
    for (int i = 0; i < 4; i++) bv[i] = bias[o0 + ty * 4 + i];
#pragma unroll
    for (int i = 0; i < 4; i++) {
        int o = o0 + ty * 4 + i;
        size_t idx = ((size_t)b * C_ + o) * N_ + n0 + tx * 4;
        __nv_bfloat162 p0, p1;
        p0.x = __float2bfloat16(acc[i][0] + bv[i]);
        p0.y = __float2bfloat16(acc[i][1] + bv[i]);
        p1.x = __float2bfloat16(acc[i][2] + bv[i]);
        p1.y = __float2bfloat16(acc[i][3] + bv[i]);
        *(__nv_bfloat162*)&Y[idx]     = p0;
        *(__nv_bfloat162*)&Y[idx + 2] = p1;
    }
}

// ---------------------------------------------------------------------------
// QK dual GEMM on mma.sync bf16 with hi/lo split (3 terms), fused exp.
// ---------------------------------------------------------------------------
#define QK_QHI_B  0
#define QK_QLO_B  (128 * 144)
#define QK_K1HI_B (256 * 144)
#define QK_K1LO_B (320 * 144)
#define QK_K2HI_B (384 * 144)
#define QK_K2LO_B (448 * 144)
#define QK_SMEM_TOTAL (512 * 144)   // 73728 B

__global__ void __launch_bounds__(256, 2)
qk_mma_kernel(float* __restrict__ E1)
{
    extern __shared__ __align__(16) char smem[];
    const uint32_t sbase = smem_u32(smem);
    const int t = threadIdx.x;
    const int wid = t / 32, lane = t % 32;
    const int wn = wid >> 1, wm = wid & 1;

    const int b  = blockIdx.z;
    const int m0 = blockIdx.x * 64;
    const int n0 = blockIdx.y * 128;

    const char* qh  = (const char*)(g_qhi  + ((size_t)b * N_ + n0) * 64);
    const char* ql  = (const char*)(g_qlo  + ((size_t)b * N_ + n0) * 64);
    const char* k1h = (const char*)(g_k1hi + ((size_t)b * N_ + m0) * 64);
    const char* k1l = (const char*)(g_k1lo + ((size_t)b * N_ + m0) * 64);
    const char* k2h = (const char*)(g_k2hi + ((size_t)b * N_ + m0) * 64);
    const char* k2l = (const char*)(g_k2lo + ((size_t)b * N_ + m0) * 64);

#pragma unroll
    for (int it = 0; it < 4; it++) {
        int idx = t + 256 * it;
        int row = idx >> 3, q = idx & 7;
        uint32_t d = sbase + (uint32_t)(row * 144 + q * 16);
        int srco = row * 128 + q * 16;
        CP_ASYNC16(d + QK_QHI_B, qh + srco);
        CP_ASYNC16(d + QK_QLO_B, ql + srco);
    }
#pragma unroll
    for (int it = 0; it < 2; it++) {
        int idx = t + 256 * it;
        int row = idx >> 3, q = idx & 7;
        uint32_t d = sbase + (uint32_t)(row * 144 + q * 16);
        int srco = row * 128 + q * 16;
        CP_ASYNC16(d + QK_K1HI_B, k1h + srco);
        CP_ASYNC16(d + QK_K1LO_B, k1l + srco);
        CP_ASYNC16(d + QK_K2HI_B, k2h + srco);
        CP_ASYNC16(d + QK_K2LO_B, k2l + srco);
    }
    CP_ASYNC_COMMIT();
    CP_ASYNC_WAIT0();
    __syncthreads();

    const int g    = lane >> 3;
    const int arow = wn * 32 + ((g & 1) ? 8 : 0) + (lane & 7);
    const int koff = (g >> 1) * 8;
    const int brow = wm * 32 + ((g & 1) ? 8 : 0) + (lane & 7);

    float acc1[2][4][4] = {}, acc2[2][4][4] = {};

#pragma unroll
    for (int kk = 0; kk < 4; kk++) {
        uint32_t ah[2][4], al[2][4];
#pragma unroll
        for (int mi = 0; mi < 2; mi++) {
            uint32_t ka = (uint32_t)((arow + mi * 16) * 144 + (kk * 16 + koff) * 2);
            LDMATRIX_X4(ah[mi][0], ah[mi][1], ah[mi][2], ah[mi][3], sbase + QK_QHI_B + ka);
            LDMATRIX_X4(al[mi][0], al[mi][1], al[mi][2], al[mi][3], sbase + QK_QLO_B + ka);
        }
#pragma unroll
        for (int j2 = 0; j2 < 2; j2++) {
            uint32_t kb = (uint32_t)((brow + j2 * 16) * 144 + (kk * 16 + koff) * 2);
            uint32_t b1h[2][2], b1l[2][2], b2h[2][2], b2l[2][2];
            {
                uint32_t r0, r1, r2, r3;
                LDMATRIX_X4(r0, r1, r2, r3, sbase + QK_K1HI_B + kb);
                b1h[0][0] = r0; b1h[0][1] = r2; b1h[1][0] = r1; b1h[1][1] = r3;
                LDMATRIX_X4(r0, r1, r2, r3, sbase + QK_K1LO_B + kb);
                b1l[0][0] = r0; b1l[0][1] = r2; b1l[1][0] = r1; b1l[1][1] = r3;
                LDMATRIX_X4(r0, r1, r2, r3, sbase + QK_K2HI_B + kb);
                b2h[0][0] = r0; b2h[0][1] = r2; b2h[1][0] = r1; b2h[1][1] = r3;
                LDMATRIX_X4(r0, r1, r2, r3, sbase + QK_K2LO_B + kb);
                b2l[0][0] = r0; b2l[0][1] = r2; b2l[1][0] = r1; b2l[1][1] = r3;
            }
#pragma unroll
            for (int mi = 0; mi < 2; mi++)
#pragma unroll
                for (int jj = 0; jj < 2; jj++) {
                    int j = j2 * 2 + jj;
                    MMA_BF16(acc1[mi][j], ah[mi], b1h[jj]);
                    MMA_BF16(acc1[mi][j], ah[mi], b1l[jj]);
                    MMA_BF16(acc1[mi][j], al[mi], b1h[jj]);
                    MMA_BF16(acc2[mi][j], ah[mi], b2h[jj]);
                    MMA_BF16(acc2[mi][j], ah[mi], b2l[jj]);
                    MMA_BF16(acc2[mi][j], al[mi], b2h[jj]);
                }
        }
    }

    const int gid = lane >> 2, tig = lane & 3;
#pragma unroll
    for (int mi = 0; mi < 2; mi++)
#pragma unroll
        for (int rr = 0; rr < 2; rr++) {
            int n = n0 + wn * 32 + mi * 16 + gid + rr * 8;
            size_t rowoff = ((size_t)b * N_ + n) * N_;
#pragma unroll
            for (int j = 0; j < 4; j++) {
                int m = m0 + wm * 32 + j * 8 + tig * 2;
                float2 e1, e2;
                e1.x = __expf(acc1[mi][j][rr * 2 + 0]);
                e1.y = __expf(acc1[mi][j][rr * 2 + 1]);
                e2.x = __expf(acc2[mi][j][rr * 2 + 0]);
                e2.y = __expf(acc2[mi][j][rr * 2 + 1]);
                *(float2*)&E1[rowoff + m]   = e1;
                *(float2*)&g_E2[rowoff + m] = e2;
            }
        }
}

// ---------------------------------------------------------------------------
// Double softmax; writes fp32 attn in place (d_out) + bf16 copy for the AV MMA.
// ---------------------------------------------------------------------------
__global__ void softmax2_kernel(float* __restrict__ attn, __nv_bfloat16* __restrict__ attn_bf)
{
    __shared__ float r1[N_];
    __shared__ float r2[N_];
    __shared__ float red[256];
    const int b = blockIdx.y, n = blockIdx.x, t = threadIdx.x;
    float* row1 = attn + ((size_t)b * N_ + n) * N_;
    const float* row2 = g_E2 + ((size_t)b * N_ + n) * N_;
    __nv_bfloat16* rowb = attn_bf + ((size_t)b * N_ + n) * N_;

    float s1 = 0.f, s2 = 0.f;
#pragma unroll
    for (int i = 0; i < 4; i++) {
        int idx = (t + 256 * i) * 4;
        float4 a = *(const float4*)&row1[idx];
        float4 c = *(const float4*)&row2[idx];
        *(float4*)&r1[idx] = a;
        *(float4*)&r2[idx] = c;
        s1 += (a.x + a.y) + (a.z + a.w);
        s2 += (c.x + c.y) + (c.z + c.w);
    }
    red[t] = s1; __syncthreads();
    for (int off = 128; off > 0; off >>= 1) { if (t < off) red[t] += red[t + off]; __syncthreads(); }
    float d1 = red[0]; __syncthreads();
    red[t] = s2; __syncthreads();
    for (int off = 128; off > 0; off >>= 1) { if (t < off) red[t] += red[t + off]; __syncthreads(); }
    float d2 = red[0]; __syncthreads();

    const float i1 = 1.f / d1, i2 = 1.f / d2;
    float s = 0.f;
#pragma unroll
    for (int i = 0; i < 4; i++) {
        int idx = (t + 256 * i) * 4;
        float4 a = *(const float4*)&r1[idx];
        float4 c = *(const float4*)&r2[idx];
        float4 e;
        e.x = __expf(a.x * i1 + c.x * i2);
        e.y = __expf(a.y * i1 + c.y * i2);
        e.z = __expf(a.z * i1 + c.z * i2);
        e.w = __expf(a.w * i1 + c.w * i2);
        *(float4*)&r1[idx] = e;
        s += (e.x + e.y) + (e.z + e.w);
    }
    red[t] = s; __syncthreads();
    for (int off = 128; off > 0; off >>= 1) { if (t < off) red[t] += red[t + off]; __syncthreads(); }
    const float invS = 1.f / red[0]; __syncthreads();

#pragma unroll
    for (int i = 0; i < 4; i++) {
        int idx = (t + 256 * i) * 4;
        float4 e = *(const float4*)&r1[idx];
        e.x *= invS; e.y *= invS; e.z *= invS; e.w *= invS;
        *(float4*)&row1[idx] = e;
        __nv_bfloat162 p0, p1;
        p0.x = __float2bfloat16(e.x); p0.y = __float2bfloat16(e.y);
        p1.x = __float2bfloat16(e.z); p1.y = __float2bfloat16(e.w);
        *(__nv_bfloat162*)&rowb[idx]     = p0;
        *(__nv_bfloat162*)&rowb[idx + 2] = p1;
    }
}

// ---------------------------------------------------------------------------
// AV dual GEMM on mma.sync bf16, fused gamma*acc + x residual.
// Block 128c x 128n, 512 threads (16 warps: 4c x 4n), warp tile 32x32.
// K chunks of 64, 3-stage cp.async pipeline. SMEM 3 x 55296 = 165888 B.
// ---------------------------------------------------------------------------
#define AV_VOFF_B   0
#define AV_WOFF_B   (128 * 144)
#define AV_AOFF_B   (256 * 144)
#define AV_STAGE_B  (384 * 144)          // 55296 B per stage
#define AV_SMEM_TOTAL (3 * AV_STAGE_B)   // 165888 B

__device__ __forceinline__ void av_issue(uint32_t sb, const __nv_bfloat16* gv,
                                         const __nv_bfloat16* gw, const __nv_bfloat16* ga,
                                         int m0, int t)
{
#pragma unroll
    for (int it = 0; it < 2; it++) {
        int idx = t + 512 * it;
        int row = idx >> 3, q = idx & 7;
        uint32_t d = sb + (uint32_t)(row * 144 + q * 16);
        CP_ASYNC16(d + AV_VOFF_B, (const char*)(gv + (size_t)row * N_ + m0) + q * 16);
        CP_ASYNC16(d + AV_WOFF_B, (const char*)(gw + (size_t)row * N_ + m0) + q * 16);
        CP_ASYNC16(d + AV_AOFF_B, (const char*)(ga + (size_t)row * N_ + m0) + q * 16);
    }
}

__global__ void __launch_bounds__(512, 1)
av_mma_kernel(const float* __restrict__ x3, const float* __restrict__ xt,
              const float* __restrict__ gma, const float* __restrict__ gma2,
              float* __restrict__ out1, float* __restrict__ out2)
{
    extern __shared__ __align__(16) char smem[];
    const uint32_t sbase = smem_u32(smem);
    const int t = threadIdx.x;
    const int wid = t / 32, lane = t % 32;
    const int wc = wid >> 2, wn = wid & 3;   // 4 warps along c, 4 along n

    const int b  = blockIdx.z;
    const int c0 = blockIdx.y * 128;
    const int n0 = blockIdx.x * 128;

    const __nv_bfloat16* vb = g_vbf    + ((size_t)b * C_ + c0) * N_;
    const __nv_bfloat16* wb = g_vtbf   + ((size_t)b * C_ + c0) * N_;
    const __nv_bfloat16* ab = g_attnbf + ((size_t)b * N_ + n0) * N_;

    float acc1[2][4][4] = {}, acc2[2][4][4] = {};

    const int g      = lane >> 3;
    const int arow   = wc * 32 + ((g & 1) ? 8 : 0) + (lane & 7);
    const int akoff  = (g >> 1) * 8;
    const int brow   = wn * 32 + ((g & 1) ? 8 : 0) + (lane & 7);
    const int bkoff  = (g >> 1) * 8;

    av_issue(sbase + 0 * AV_STAGE_B, vb, wb, ab, 0,  t); CP_ASYNC_COMMIT();
    av_issue(sbase + 1 * AV_STAGE_B, vb, wb, ab, 64, t); CP_ASYNC_COMMIT();

    int stage = 0;
    for (int i = 0; i < 64; i++) {
        if (i + 2 < 64) {
            int s2 = stage + 2; if (s2 >= 3) s2 -= 3;
            av_issue(sbase + s2 * AV_STAGE_B, vb, wb, ab, (i + 2) * 64, t);
            CP_ASYNC_COMMIT();
            CP_ASYNC_WAIT2();
        } else if (i + 1 < 64) {
            CP_ASYNC_WAIT1();
        } else {
            CP_ASYNC_WAIT0();
        }
        __syncthreads();

        const uint32_t st = sbase + stage * AV_STAGE_B;
#pragma unroll
        for (int kk = 0; kk < 4; kk++) {
            uint32_t av[2][4], aw[2][4], bfr[4][2];
#pragma unroll
            for (int mi = 0; mi < 2; mi++) {
                uint32_t roff = (uint32_t)((arow + mi * 16) * 144 + (kk * 16 + akoff) * 2);
                LDMATRIX_X4(av[mi][0], av[mi][1], av[mi][2], av[mi][3], st + AV_VOFF_B + roff);
                LDMATRIX_X4(aw[mi][0], aw[mi][1], aw[mi][2], aw[mi][3], st + AV_WOFF_B + roff);
            }
#pragma unroll
            for (int j2 = 0; j2 < 2; j2++) {
                uint32_t r0, r1, r2, r3;
                uint32_t baddr = st + AV_AOFF_B +
                    (uint32_t)((brow + j2 * 16) * 144 + (kk * 16 + bkoff) * 2);
                LDMATRIX_X4(r0, r1, r2, r3, baddr);
                bfr[j2 * 2 + 0][0] = r0; bfr[j2 * 2 + 0][1] = r2;
                bfr[j2 * 2 + 1][0] = r1; bfr[j2 * 2 + 1][1] = r3;
            }
#pragma unroll
            for (int mi = 0; mi < 2; mi++)
#pragma unroll
                for (int j = 0; j < 4; j++) {
                    MMA_BF16(acc1[mi][j], av[mi], bfr[j]);
                    MMA_BF16(acc2[mi][j], aw[mi], bfr[j]);
                }
        }
        __syncthreads();
        if (++stage == 3) stage = 0;
    }

    const float gv1 = gma[0], gv2 = gma2[0];
    const int gid = lane >> 2, tig = lane & 3;
#pragma unroll
    for (int mi = 0; mi < 2; mi++) {
#pragma unroll
        for (int rr = 0; rr < 2; rr++) {
            int c = c0 + wc * 32 + mi * 16 + gid + rr * 8;
            size_t rowoff = ((size_t)b * C_ + c) * N_;
#pragma unroll
            for (int j = 0; j < 4; j++) {
                int n = n0 + wn * 32 + j * 8 + tig * 2;
                float2 xv = *(const float2*)&x3[rowoff + n];
                float2 o1;
                o1.x = gv1 * acc1[mi][j][rr * 2 + 0] + xv.x;
                o1.y = gv1 * acc1[mi][j][rr * 2 + 1] + xv.y;
                *(float2*)&out1[rowoff + n] = o1;
                float2 xtv = *(const float2*)&xt[rowoff + n];
                float2 o2;
                o2.x = gv2 * acc2[mi][j][rr * 2 + 0] + xtv.x;
                o2.y = gv2 * acc2[mi][j][rr * 2 + 1] + xtv.y;
                *(float2*)&out2[rowoff + n] = o2;
            }
        }
    }
}

// ---------------------------------------------------------------------------
extern "C" void kernel_launch(void* const* d_in, const int* in_sizes, int n_in,
                              void* d_out, int out_size)
{
    const float* x1  = (const float*)d_in[0];
    const float* x2  = (const float*)d_in[1];
    const float* x3  = (const float*)d_in[2];
    const float* xt  = (const float*)d_in[3];
    const float* Wq  = (const float*)d_in[4];
    const float* bq  = (const float*)d_in[5];
    const float* Wk  = (const float*)d_in[6];
    const float* bk  = (const float*)d_in[7];
    const float* Wk2 = (const float*)d_in[8];
    const float* bk2 = (const float*)d_in[9];
    const float* Wv  = (const float*)d_in[10];
    const float* bv  = (const float*)d_in[11];
    const float* Wv2 = (const float*)d_in[12];
    const float* bv2 = (const float*)d_in[13];
    const float* gamma  = (const float*)d_in[14];
    const float* gamma2 = (const float*)d_in[15];

    float* attn = (float*)d_out;
    float* out1 = attn + ATTN_ELEMS;
    float* out2 = out1 + OUT_ELEMS;

    __nv_bfloat16 *qhi, *qlo, *k1hi, *k1lo, *k2hi, *k2lo, *vbf, *vtbf, *attnbf;
    cudaGetSymbolAddress((void**)&qhi,    g_qhi);
    cudaGetSymbolAddress((void**)&qlo,    g_qlo);
    cudaGetSymbolAddress((void**)&k1hi,   g_k1hi);
    cudaGetSymbolAddress((void**)&k1lo,   g_k1lo);
    cudaGetSymbolAddress((void**)&k2hi,   g_k2hi);
    cudaGetSymbolAddress((void**)&k2lo,   g_k2lo);
    cudaGetSymbolAddress((void**)&vbf,    g_vbf);
    cudaGetSymbolAddress((void**)&vtbf,   g_vtbf);
    cudaGetSymbolAddress((void**)&attnbf, g_attnbf);

    // Side stream + events for overlapping the v/vt projections with the
    // q/k -> QK -> softmax chain. Created once (host resources only).
    static cudaStream_t s1 = nullptr;
    static cudaEvent_t ev_fork = nullptr, ev_join = nullptr;
    if (s1 == nullptr) {
        cudaStreamCreateWithFlags(&s1, cudaStreamNonBlocking);
        cudaEventCreateWithFlags(&ev_fork, cudaEventDisableTiming);
        cudaEventCreateWithFlags(&ev_join, cudaEventDisableTiming);
    }

    dim3 blk(256);

    // fork: v/vt projections on side stream
    cudaEventRecord(ev_fork, 0);
    cudaStreamWaitEvent(s1, ev_fork, 0);
    proj_v_kernel<<<dim3(N_ / 64, C_ / 64, B_), blk, 0, s1>>>(Wv,  bv,  x3, vbf);
    proj_v_kernel<<<dim3(N_ / 64, C_ / 64, B_), blk, 0, s1>>>(Wv2, bv2, xt, vtbf);
    cudaEventRecord(ev_join, s1);

    // main chain: q/k projections -> QK -> softmax
    proj_qk_kernel<<<dim3(N_ / 64, 1, B_), blk>>>(Wq,  bq,  x3, qhi,  qlo);
    proj_qk_kernel<<<dim3(N_ / 64, 1, B_), blk>>>(Wk,  bk,  x1, k1hi, k1lo);
    proj_qk_kernel<<<dim3(N_ / 64, 1, B_), blk>>>(Wk2, bk2, x2, k2hi, k2lo);

    cudaFuncSetAttribute(qk_mma_kernel, cudaFuncAttributeMaxDynamicSharedMemorySize, QK_SMEM_TOTAL);
    qk_mma_kernel<<<dim3(N_ / 64, N_ / 128, B_), blk, QK_SMEM_TOTAL>>>(attn);

    softmax2_kernel<<<dim3(N_, B_), blk>>>(attn, attnbf);

    // join: AV needs vbf/vtbf
    cudaStreamWaitEvent(0, ev_join, 0);

    cudaFuncSetAttribute(av_mma_kernel, cudaFuncAttributeMaxDynamicSharedMemorySize, AV_SMEM_TOTAL);
    av_mma_kernel<<<dim3(N_ / 128, C_ / 128, B_), dim3(512), AV_SMEM_TOTAL>>>(
        x3, xt, gamma, gamma2, out1, out2);
}